// round 15
// baseline (speedup 1.0000x reference)
#include <cuda_runtime.h>
#include <stdint.h>
#include <math.h>

#define BATCH 8
#define SEQ   16
#define NH    16
#define HD    128
#define DIM   2048
#define DIM3  6144
#define CACHE 4096
#define TTOT  4112
#define NTOK  128
#define NSPL  7

#define KH_OFF (NTOK*DIM)
#define KH_ELEMS (BATCH*NH*TTOT*HD)
#define VH_OFF (KH_OFF + KH_ELEMS)

typedef unsigned long long u64;

__device__ float g_qkv[NTOK * DIM3];            // 3 MB
__device__ float g_ctx[NTOK * DIM];             // 1 MB
__device__ float g_part[4 * NTOK * DIM3];       // split-K partials
__device__ float g_pacc[BATCH*NH*NSPL*SEQ*HD];  // attn partial ctx
__device__ float g_pm[BATCH*NH*NSPL*SEQ];
__device__ float g_pl[BATCH*NH*NSPL*SEQ];

// ---------- packed f32x2 helpers (sm_103a) ----------
__device__ __forceinline__ u64 pk2(float lo, float hi) {
    u64 r; asm("mov.b64 %0, {%1, %2};" : "=l"(r) : "f"(lo), "f"(hi)); return r;
}
__device__ __forceinline__ void upk2(u64 v, float& lo, float& hi) {
    asm("mov.b64 {%0, %1}, %2;" : "=f"(lo), "=f"(hi) : "l"(v));
}
__device__ __forceinline__ u64 ffma2(u64 a, u64 b, u64 c) {
    u64 d; asm("fma.rn.f32x2 %0, %1, %2, %3;" : "=l"(d) : "l"(a), "l"(b), "l"(c)); return d;
}
__device__ __forceinline__ u64 fmul2(u64 a, u64 b) {
    u64 d; asm("mul.rn.f32x2 %0, %1, %2;" : "=l"(d) : "l"(a), "l"(b)); return d;
}
__device__ __forceinline__ u64 fadd2(u64 a, u64 b) {
    u64 d; asm("add.rn.f32x2 %0, %1, %2;" : "=l"(d) : "l"(a), "l"(b)); return d;
}

// ---------- cp.async helpers ----------
__device__ __forceinline__ void cpa16(void* smem_dst, const void* gmem_src) {
    unsigned int su = (unsigned int)__cvta_generic_to_shared(smem_dst);
    asm volatile("cp.async.cg.shared.global [%0], [%1], 16;" :: "r"(su), "l"(gmem_src));
}
#define CP_COMMIT() asm volatile("cp.async.commit_group;")
#define CP_WAIT(N)  asm volatile("cp.async.wait_group %0;" :: "n"(N))

// ---------- bulk smem->gmem copy (TMA engine) ----------
__device__ __forceinline__ void bulk_store(void* gmem_dst, const void* smem_src,
                                           unsigned int bytes) {
    unsigned int su = (unsigned int)__cvta_generic_to_shared(smem_src);
    asm volatile("cp.async.bulk.global.shared::cta.bulk_group [%0], [%1], %2;"
                 :: "l"(gmem_dst), "r"(su), "r"(bytes) : "memory");
}
#define BULK_COMMIT()     asm volatile("cp.async.bulk.commit_group;" ::: "memory")
#define BULK_WAIT_READ0() asm volatile("cp.async.bulk.wait_group.read 0;" ::: "memory")
#define BULK_WAIT_ALL()   asm volatile("cp.async.bulk.wait_group 0;" ::: "memory")
__device__ __forceinline__ void fence_proxy_async_sh() {
    asm volatile("fence.proxy.async.shared::cta;" ::: "memory");
}

// ---------- bfly8 ----------
__device__ __forceinline__ float bfly8(const float p[8], int dc) {
    const unsigned FULL = 0xffffffffu;
    bool b4 = (dc & 4) != 0;
    float r4[4];
    #pragma unroll
    for (int i = 0; i < 4; i++) {
        float send = b4 ? p[i] : p[i+4];
        float recv = __shfl_xor_sync(FULL, send, 4);
        r4[i] = (b4 ? p[i+4] : p[i]) + recv;
    }
    bool b2 = (dc & 2) != 0;
    float r2[2];
    #pragma unroll
    for (int i = 0; i < 2; i++) {
        float send = b2 ? r4[i] : r4[i+2];
        float recv = __shfl_xor_sync(FULL, send, 2);
        r2[i] = (b2 ? r4[i+2] : r4[i]) + recv;
    }
    bool b1 = (dc & 1) != 0;
    float send = b1 ? r2[0] : r2[1];
    float recv = __shfl_xor_sync(FULL, send, 1);
    return (b1 ? r2[1] : r2[0]) + recv;
}

// ---------- split-K GEMM ----------
template<int KSLICE>
__global__ void __launch_bounds__(256)
gemm_splitk(const float* __restrict__ A, const float* __restrict__ Bw,
            float* __restrict__ Cpart, int N)
{
    constexpr int BN = 64, BK = 16;
    __shared__ float As[BK][NTOK];
    __shared__ float Bs[BK][BN];
    int tid = threadIdx.x;
    int n0 = blockIdx.x * BN;
    int kbase = blockIdx.y * KSLICE;
    int K = gridDim.y * KSLICE;
    int tx = tid & 15, ty = tid >> 4;

    u64 acc[4][4];
    #pragma unroll
    for (int i = 0; i < 4; i++)
        #pragma unroll
        for (int j = 0; j < 4; j++) acc[i][j] = 0ULL;

    for (int k0 = kbase; k0 < kbase + KSLICE; k0 += BK) {
        #pragma unroll
        for (int j = 0; j < 2; j++) {
            int lin = tid + j * 256;
            int am = lin & 127, k4 = (lin >> 7) * 4;
            float4 av = *(const float4*)&A[am * K + k0 + k4];
            As[k4+0][am] = av.x; As[k4+1][am] = av.y;
            As[k4+2][am] = av.z; As[k4+3][am] = av.w;
        }
        {
            int bk = tid >> 4, bn = (tid & 15) * 4;
            *(float4*)&Bs[bk][bn] = *(const float4*)&Bw[(k0 + bk) * N + n0 + bn];
        }
        __syncthreads();
        #pragma unroll
        for (int k = 0; k < BK; k++) {
            ulonglong2 a01 = *(const ulonglong2*)&As[k][ty*8];
            ulonglong2 a23 = *(const ulonglong2*)&As[k][ty*8 + 4];
            float4 bf = *(const float4*)&Bs[k][tx*4];
            u64 b0 = pk2(bf.x, bf.x), b1 = pk2(bf.y, bf.y);
            u64 b2 = pk2(bf.z, bf.z), b3 = pk2(bf.w, bf.w);
            acc[0][0] = ffma2(a01.x, b0, acc[0][0]);
            acc[0][1] = ffma2(a01.x, b1, acc[0][1]);
            acc[0][2] = ffma2(a01.x, b2, acc[0][2]);
            acc[0][3] = ffma2(a01.x, b3, acc[0][3]);
            acc[1][0] = ffma2(a01.y, b0, acc[1][0]);
            acc[1][1] = ffma2(a01.y, b1, acc[1][1]);
            acc[1][2] = ffma2(a01.y, b2, acc[1][2]);
            acc[1][3] = ffma2(a01.y, b3, acc[1][3]);
            acc[2][0] = ffma2(a23.x, b0, acc[2][0]);
            acc[2][1] = ffma2(a23.x, b1, acc[2][1]);
            acc[2][2] = ffma2(a23.x, b2, acc[2][2]);
            acc[2][3] = ffma2(a23.x, b3, acc[2][3]);
            acc[3][0] = ffma2(a23.y, b0, acc[3][0]);
            acc[3][1] = ffma2(a23.y, b1, acc[3][1]);
            acc[3][2] = ffma2(a23.y, b2, acc[3][2]);
            acc[3][3] = ffma2(a23.y, b3, acc[3][3]);
        }
        __syncthreads();
    }
    float* cp = Cpart + (size_t)blockIdx.y * NTOK * N;
    #pragma unroll
    for (int mp = 0; mp < 4; mp++) {
        float lo[4], hi[4];
        #pragma unroll
        for (int j = 0; j < 4; j++) upk2(acc[mp][j], lo[j], hi[j]);
        int m = ty * 8 + mp * 2;
        float4 w0 = {lo[0], lo[1], lo[2], lo[3]};
        float4 w1 = {hi[0], hi[1], hi[2], hi[3]};
        *(float4*)&cp[(m+0) * N + n0 + tx*4] = w0;
        *(float4*)&cp[(m+1) * N + n0 + tx*4] = w1;
    }
}

// ---------- split-K reduce ----------
template<int NS>
__global__ void __launch_bounds__(256)
reduce_part(const float* __restrict__ Cpart, const float* __restrict__ bias,
            float* __restrict__ C, int N)
{
    int idx = blockIdx.x * 256 + threadIdx.x;
    int n4 = N / 4;
    int m = idx / n4, n = (idx % n4) * 4;
    float4 s = *(const float4*)&bias[n];
    #pragma unroll
    for (int sp = 0; sp < NS; sp++) {
        float4 p = *(const float4*)&Cpart[(size_t)sp * NTOK * N + m * N + n];
        s.x += p.x; s.y += p.y; s.z += p.z; s.w += p.w;
    }
    *(float4*)&C[m * N + n] = s;
}

// dummy: shifts launch indices so ncu's fixed profile slot lands on attn_split
__global__ void dummy_k() {}

#define SCP 18
#define KHALF (16*HD)   // floats per K half-buffer

// ---------- split-KV flash attention; K half-tile triple-buffer; 4 CTAs/SM ----------
__global__ void __launch_bounds__(256, 4)
attn_split(const float* __restrict__ kc, const float* __restrict__ vc,
           float* __restrict__ out)
{
    extern __shared__ float sm[];
    float* Kb = sm;                       // 3 × 16×128 = 6144 floats
    float* Vb = sm + 3*KHALF;             // 32×128 = 4096
    float* Qs = Vb + 32*HD;               // 2048
    float* Sc = Qs + SEQ*HD;              // 576
    float* Ps = Sc + 32*SCP;              // 512
    float* corr_sm = Ps + SEQ*32;         // 16

    int sp = blockIdx.x, h = blockIdx.y, b = blockIdx.z;
    int tid = threadIdx.x;
    int s = tid >> 4, dg = tid & 15;      // softmax role
    int warp = tid >> 5, lane = tid & 31;
    int a_k = warp * 4 + (lane >> 3);     // stage A global key 0..31
    int dc  = lane & 7;                   // stage A d-chunk
    int kh  = tid >> 7;                   // stage B key half
    int bs  = (tid >> 3) & 15;            // stage B query
    int d8  = tid & 7;                    // stage B d-chunk
    int w8 = tid >> 5;                    // V copy rows
    int c4 = (tid & 31) * 4;              // copy cols

    int tb = sp * 19;
    int te = min(tb + 19, 129);

    u64 bacc[8];
    #pragma unroll
    for (int j = 0; j < 8; j++) bacc[j] = 0ULL;
    float m_r = -INFINITY, l_r = 0.f;
    const float SCALE = 0.08838834764831845f;

    const float* kcb  = &kc[(size_t)(b*NH + h) * CACHE * HD];
    const float* vcb  = &vc[(size_t)(b*NH + h) * CACHE * HD];
    const float* qkvK = &g_qkv[(size_t)(b*SEQ)*DIM3 +   DIM + h*HD];
    const float* qkvV = &g_qkv[(size_t)(b*SEQ)*DIM3 + 2*DIM + h*HD];
    float* khout = &out[KH_OFF + (size_t)(b*NH + h) * TTOT * HD];
    float* vhout = &out[VH_OFF + (size_t)(b*NH + h) * TTOT * HD];

    // issue one 16-key K half (hh = global half index); skipped if out of range
    auto issueKh = [&](int hh) {
        if (hh >= 2*te) return;
        float* dst = Kb + (hh % 3) * KHALF;
        if (hh < 256) {                   // entirely inside cache
            const float* src = kcb + (size_t)hh * 16 * HD;
            #pragma unroll
            for (int i = 0; i < 2; i++) {
                int slot = tid + i * 256;
                int r = slot >> 5, c = (slot & 31) * 4;
                cpa16(dst + r*HD + c, src + (size_t)r*HD + c);
            }
        } else {                          // tail halves (new tokens / clamp)
            #pragma unroll
            for (int i = 0; i < 2; i++) {
                int slot = tid + i * 256;
                int r = slot >> 5, c = (slot & 31) * 4;
                int t = hh * 16 + r;
                int tc = t < TTOT ? t : TTOT - 1;
                const float* srcp = (tc < CACHE) ? (kcb + (size_t)tc*HD + c)
                                                 : (qkvK + (size_t)(tc-CACHE)*DIM3 + c);
                cpa16(dst + r*HD + c, srcp);
            }
        }
    };
    auto issueV = [&](int tile) {
        if (tile >= te) return;
        bool tail = (tile == 128);
        if (!tail) {
            const float* src = vcb + (size_t)tile * 32 * HD + (size_t)w8 * HD + c4;
            #pragma unroll
            for (int i = 0; i < 4; i++)
                cpa16(Vb + (w8 + 8*i)*HD + c4, src + (size_t)(8*i)*HD);
        } else {
            #pragma unroll
            for (int i = 0; i < 4; i++) {
                int rr = w8 + 8*i;
                int t = tile * 32 + rr;
                int tc = t < TTOT ? t : TTOT - 1;
                const float* src = (tc < CACHE) ? (vcb + (size_t)tc*HD + c4)
                                                : (qkvV + (size_t)(tc-CACHE)*DIM3 + c4);
                cpa16(Vb + rr*HD + c4, src);
            }
        }
    };

    // stage Q tile into smem (once)
    #pragma unroll
    for (int i = 0; i < 2; i++) {
        int lin = tid + i * 256;
        int q = lin >> 5, c = (lin & 31) * 4;
        *(float4*)&Qs[q*HD + c] = *(const float4*)&g_qkv[(size_t)(b*SEQ + q)*DIM3 + h*HD + c];
    }

    // prologue: visible {Kh(2tb), Kh(2tb+1)}; pending [V(tb), Kh(2tb+2)]
    issueKh(2*tb);     CP_COMMIT();
    issueKh(2*tb + 1); CP_COMMIT();
    issueV(tb);        CP_COMMIT();
    issueKh(2*tb + 2); CP_COMMIT();
    CP_WAIT(2);
    __syncthreads();

    for (int tile = tb; tile < te; tile++) {
        int t0 = tile * 32;
        const float* KtA = Kb + ((2*tile    ) % 3) * KHALF;
        const float* KtB = Kb + ((2*tile + 1) % 3) * KHALF;

        // ---- K copy-out via bulk engine (read-read with stage A) ----
        if (tid == 0) {
            fence_proxy_async_sh();
            bulk_store(khout + (size_t)t0 * HD, KtA, 16u*HD*4u);
            if (tile < 128)
                bulk_store(khout + (size_t)(t0 + 16) * HD, KtB, 16u*HD*4u);
            BULK_COMMIT();
        }

        // ---- stage A: warps 0-3 on KtA (keys 0-15), warps 4-7 on KtB ----
        {
            const float* Kt = (warp < 4) ? KtA : KtB;
            int lk = a_k & 15;
            u64 kreg[8];
            #pragma unroll
            for (int j = 0; j < 4; j++) {
                ulonglong2 kv = *(const ulonglong2*)&Kt[lk*HD + j*32 + dc*4];
                kreg[2*j] = kv.x; kreg[2*j+1] = kv.y;
            }
            #pragma unroll
            for (int g = 0; g < 2; g++) {
                float p[8];
                #pragma unroll
                for (int qq = 0; qq < 8; qq++) {
                    int q = g*8 + qq;
                    u64 dv = 0ULL;
                    #pragma unroll
                    for (int j = 0; j < 4; j++) {
                        ulonglong2 qv = *(const ulonglong2*)&Qs[q*HD + j*32 + dc*4];
                        dv = ffma2(kreg[2*j],   qv.x, dv);
                        dv = ffma2(kreg[2*j+1], qv.y, dv);
                    }
                    float lo, hi; upk2(dv, lo, hi);
                    p[qq] = lo + hi;
                }
                float sq = bfly8(p, dc);
                Sc[a_k*SCP + g*8 + dc] = sq;
            }
        }
        __syncthreads();

        // ---- softmax ----
        float sc0 = Sc[dg*SCP + s] * SCALE;
        float sc1 = Sc[(dg+16)*SCP + s] * SCALE;
        if (tile == 128) {
            if (t0 + dg > CACHE + s)      sc0 = -INFINITY;
            if (t0 + 16 + dg > CACHE + s) sc1 = -INFINITY;
        }
        float tmax = fmaxf(m_r, fmaxf(sc0, sc1));
        tmax = fmaxf(tmax, __shfl_xor_sync(0xffffffffu, tmax, 1));
        tmax = fmaxf(tmax, __shfl_xor_sync(0xffffffffu, tmax, 2));
        tmax = fmaxf(tmax, __shfl_xor_sync(0xffffffffu, tmax, 4));
        tmax = fmaxf(tmax, __shfl_xor_sync(0xffffffffu, tmax, 8));
        float corr = __expf(m_r - tmax);
        m_r = tmax;
        float e0 = __expf(sc0 - tmax);
        float e1 = __expf(sc1 - tmax);
        Ps[s*32 + dg]      = e0;
        Ps[s*32 + dg + 16] = e1;
        if (dg == 0) corr_sm[s] = corr;
        float lsum = e0 + e1;
        lsum += __shfl_xor_sync(0xffffffffu, lsum, 1);
        lsum += __shfl_xor_sync(0xffffffffu, lsum, 2);
        lsum += __shfl_xor_sync(0xffffffffu, lsum, 4);
        lsum += __shfl_xor_sync(0xffffffffu, lsum, 8);
        l_r = l_r * corr + lsum;

        CP_WAIT(1);                      // V(i) done; pending [Kh(2i+2)]
        __syncthreads();

        // ---- V copy-out via bulk engine ----
        if (tid == 0) {
            fence_proxy_async_sh();
            bulk_store(vhout + (size_t)t0 * HD, Vb,
                       (tile < 128) ? 32u*HD*4u : 16u*HD*4u);
            BULK_COMMIT();
        }

        // ---- stage B ----
        {
            float cq = corr_sm[bs];
            u64 c2 = pk2(cq, cq);
            #pragma unroll
            for (int j = 0; j < 8; j++) bacc[j] = fmul2(bacc[j], c2);
            const float4* Pp = (const float4*)&Ps[bs*32 + kh*16];
            #pragma unroll
            for (int gg = 0; gg < 2; gg++) {
                float4 P4[2];
                P4[0] = Pp[gg*2]; P4[1] = Pp[gg*2 + 1];
                #pragma unroll
                for (int g = 0; g < 2; g++) {
                    #pragma unroll
                    for (int jj = 0; jj < 4; jj++) {
                        int k = kh*16 + gg*8 + g*4 + jj;
                        float pj = (jj == 0) ? P4[g].x : (jj == 1) ? P4[g].y
                                 : (jj == 2) ? P4[g].z : P4[g].w;
                        u64 pp = pk2(pj, pj);
                        #pragma unroll
                        for (int j = 0; j < 4; j++) {
                            ulonglong2 vv = *(const ulonglong2*)&Vb[k*HD + j*32 + d8*4];
                            bacc[2*j]   = ffma2(pp, vv.x, bacc[2*j]);
                            bacc[2*j+1] = ffma2(pp, vv.y, bacc[2*j+1]);
                        }
                    }
                }
            }
        }

        // ---- bulk engine must finish READING KtA/KtB/Vb before refill ----
        if (tid == 0) BULK_WAIT_READ0();
        __syncthreads();

        // ---- epilogue issues: [Kh(2i+3), V(i+1), Kh(2i+4)] ----
        issueKh(2*tile + 3); CP_COMMIT();
        issueV(tile + 1);    CP_COMMIT();
        issueKh(2*tile + 4); CP_COMMIT();
        CP_WAIT(2);          // completes Kh(2i+2), Kh(2i+3); pending [V(i+1), Kh(2i+4)]
        __syncthreads();
    }

    if (tid == 0) BULK_WAIT_READ0();
    __syncthreads();

    int pbq = ((b*NH + h) * NSPL + sp) * SEQ;
    if (dg == 0) { g_pm[pbq + s] = m_r; g_pl[pbq + s] = l_r; }

    float* comb = Kb;                     // 8KB scratch inside 24KB K region
    if (kh == 1) {
        u64* dst = (u64*)&comb[(tid & 127) * 16];
        #pragma unroll
        for (int j = 0; j < 8; j++) dst[j] = bacc[j];
    }
    __syncthreads();
    if (kh == 0) {
        const u64* src = (const u64*)&comb[(tid & 127) * 16];
        #pragma unroll
        for (int j = 0; j < 8; j++) bacc[j] = fadd2(bacc[j], src[j]);
        float* orow = &g_pacc[(size_t)(pbq + bs) * HD];
        #pragma unroll
        for (int j = 0; j < 4; j++) {
            float lo0, hi0, lo1, hi1;
            upk2(bacc[2*j], lo0, hi0);
            upk2(bacc[2*j+1], lo1, hi1);
            float4 w = {lo0, hi0, lo1, hi1};
            *(float4*)&orow[j*32 + d8*4] = w;
        }
    }
    __syncthreads();
    if (tid == 0) BULK_WAIT_ALL();
}

// ---------- combine split-KV partials -> g_ctx ----------
__global__ void __launch_bounds__(256)
attn_combine()
{
    int h = blockIdx.x, b = blockIdx.y;
    int tid = threadIdx.x;
    int s = tid >> 4, dg = tid & 15;
    int base = ((b*NH + h) * NSPL) * SEQ + s;

    float m[NSPL], l[NSPL];
    #pragma unroll
    for (int sp = 0; sp < NSPL; sp++) {
        m[sp] = g_pm[base + sp*SEQ];
        l[sp] = g_pl[base + sp*SEQ];
    }
    float M = m[0];
    #pragma unroll
    for (int sp = 1; sp < NSPL; sp++) M = fmaxf(M, m[sp]);
    float L = 0.f, w[NSPL];
    #pragma unroll
    for (int sp = 0; sp < NSPL; sp++) { w[sp] = __expf(m[sp] - M); L += w[sp] * l[sp]; }

    float o[8] = {0,0,0,0,0,0,0,0};
    #pragma unroll
    for (int sp = 0; sp < NSPL; sp++) {
        size_t pb = (size_t)(base + sp*SEQ) * HD;
        float4 a0 = *(const float4*)&g_pacc[pb + 4*dg];
        float4 a1 = *(const float4*)&g_pacc[pb + 64 + 4*dg];
        o[0] += w[sp]*a0.x; o[1] += w[sp]*a0.y; o[2] += w[sp]*a0.z; o[3] += w[sp]*a0.w;
        o[4] += w[sp]*a1.x; o[5] += w[sp]*a1.y; o[6] += w[sp]*a1.z; o[7] += w[sp]*a1.w;
    }
    float inv = 1.0f / L;
    float* cb = &g_ctx[(b*SEQ + s)*DIM + h*HD];
    float4 w0 = {o[0]*inv, o[1]*inv, o[2]*inv, o[3]*inv};
    float4 w1 = {o[4]*inv, o[5]*inv, o[6]*inv, o[7]*inv};
    *(float4*)&cb[4*dg] = w0;
    *(float4*)&cb[64 + 4*dg] = w1;
}

extern "C" void kernel_launch(void* const* d_in, const int* in_sizes, int n_in,
                              void* d_out, int out_size)
{
    const float* x      = (const float*)d_in[0];
    const float* kc     = (const float*)d_in[1];
    const float* vc     = (const float*)d_in[2];
    const float* W_attn = (const float*)d_in[3];
    const float* b_attn = (const float*)d_in[4];
    const float* W_proj = (const float*)d_in[5];
    const float* b_proj = (const float*)d_in[6];
    float* out = (float*)d_out;

    float *p_qkv, *p_ctx, *p_part;
    cudaGetSymbolAddress((void**)&p_qkv,  g_qkv);
    cudaGetSymbolAddress((void**)&p_ctx,  g_ctx);
    cudaGetSymbolAddress((void**)&p_part, g_part);

    // 3×K-half + V + Qs + Sc + Ps + corr = 13392 floats = 53568 B  (4 CTAs/SM)
    const int ATTN_SMEM = (3*KHALF + 32*HD + SEQ*HD + 32*SCP + SEQ*32 + 16) * 4;
    cudaFuncSetAttribute(attn_split, cudaFuncAttributeMaxDynamicSharedMemorySize, ATTN_SMEM);

    gemm_splitk<512><<<dim3(DIM3/64, 4), 256>>>(x, W_attn, p_part, DIM3);        // #0
    reduce_part<4><<<(NTOK*DIM3/4)/256, 256>>>(p_part, b_attn, p_qkv, DIM3);     // #1
    dummy_k<<<1, 32>>>();                                                        // #2
    attn_split<<<dim3(NSPL, NH, BATCH), 256, ATTN_SMEM>>>(kc, vc, out);          // #3
    attn_combine<<<dim3(NH, BATCH), 256>>>();                                    // #4
    gemm_splitk<256><<<dim3(DIM/64, 8), 256>>>(p_ctx, W_proj, p_part, DIM);      // #5
    reduce_part<8><<<(NTOK*DIM/4)/256, 256>>>(p_part, b_proj, out, DIM);         // #6
}

// round 16
// speedup vs baseline: 1.0771x; 1.0771x over previous
#include <cuda_runtime.h>
#include <stdint.h>
#include <math.h>

#define BATCH 8
#define SEQ   16
#define NH    16
#define HD    128
#define DIM   2048
#define DIM3  6144
#define CACHE 4096
#define TTOT  4112
#define NTOK  128
#define NSPL  7

#define KH_OFF (NTOK*DIM)
#define KH_ELEMS (BATCH*NH*TTOT*HD)
#define VH_OFF (KH_OFF + KH_ELEMS)

typedef unsigned long long u64;

__device__ float g_qkv[NTOK * DIM3];            // 3 MB
__device__ float g_ctx[NTOK * DIM];             // 1 MB
__device__ float g_part[8 * NTOK * DIM3];       // split-K partials (8 slices)
__device__ float g_pacc[BATCH*NH*NSPL*SEQ*HD];  // attn partial ctx
__device__ float g_pm[BATCH*NH*NSPL*SEQ];
__device__ float g_pl[BATCH*NH*NSPL*SEQ];

// ---------- packed f32x2 helpers (sm_103a) ----------
__device__ __forceinline__ u64 pk2(float lo, float hi) {
    u64 r; asm("mov.b64 %0, {%1, %2};" : "=l"(r) : "f"(lo), "f"(hi)); return r;
}
__device__ __forceinline__ void upk2(u64 v, float& lo, float& hi) {
    asm("mov.b64 {%0, %1}, %2;" : "=f"(lo), "=f"(hi) : "l"(v));
}
__device__ __forceinline__ u64 ffma2(u64 a, u64 b, u64 c) {
    u64 d; asm("fma.rn.f32x2 %0, %1, %2, %3;" : "=l"(d) : "l"(a), "l"(b), "l"(c)); return d;
}
__device__ __forceinline__ u64 fmul2(u64 a, u64 b) {
    u64 d; asm("mul.rn.f32x2 %0, %1, %2;" : "=l"(d) : "l"(a), "l"(b)); return d;
}
__device__ __forceinline__ u64 fadd2(u64 a, u64 b) {
    u64 d; asm("add.rn.f32x2 %0, %1, %2;" : "=l"(d) : "l"(a), "l"(b)); return d;
}

// ---------- cp.async helpers ----------
__device__ __forceinline__ void cpa16(void* smem_dst, const void* gmem_src) {
    unsigned int su = (unsigned int)__cvta_generic_to_shared(smem_dst);
    asm volatile("cp.async.cg.shared.global [%0], [%1], 16;" :: "r"(su), "l"(gmem_src));
}
#define CP_COMMIT() asm volatile("cp.async.commit_group;")
#define CP_WAIT(N)  asm volatile("cp.async.wait_group %0;" :: "n"(N))

// ---------- bulk smem->gmem copy (TMA engine) ----------
__device__ __forceinline__ void bulk_store(void* gmem_dst, const void* smem_src,
                                           unsigned int bytes) {
    unsigned int su = (unsigned int)__cvta_generic_to_shared(smem_src);
    asm volatile("cp.async.bulk.global.shared::cta.bulk_group [%0], [%1], %2;"
                 :: "l"(gmem_dst), "r"(su), "r"(bytes) : "memory");
}
#define BULK_COMMIT()     asm volatile("cp.async.bulk.commit_group;" ::: "memory")
#define BULK_WAIT_READ0() asm volatile("cp.async.bulk.wait_group.read 0;" ::: "memory")
#define BULK_WAIT_ALL()   asm volatile("cp.async.bulk.wait_group 0;" ::: "memory")
__device__ __forceinline__ void fence_proxy_async_sh() {
    asm volatile("fence.proxy.async.shared::cta;" ::: "memory");
}

// ---------- bfly8 ----------
__device__ __forceinline__ float bfly8(const float p[8], int dc) {
    const unsigned FULL = 0xffffffffu;
    bool b4 = (dc & 4) != 0;
    float r4[4];
    #pragma unroll
    for (int i = 0; i < 4; i++) {
        float send = b4 ? p[i] : p[i+4];
        float recv = __shfl_xor_sync(FULL, send, 4);
        r4[i] = (b4 ? p[i+4] : p[i]) + recv;
    }
    bool b2 = (dc & 2) != 0;
    float r2[2];
    #pragma unroll
    for (int i = 0; i < 2; i++) {
        float send = b2 ? r4[i] : r4[i+2];
        float recv = __shfl_xor_sync(FULL, send, 2);
        r2[i] = (b2 ? r4[i+2] : r4[i]) + recv;
    }
    bool b1 = (dc & 1) != 0;
    float send = b1 ? r2[0] : r2[1];
    float recv = __shfl_xor_sync(FULL, send, 1);
    return (b1 ? r2[1] : r2[0]) + recv;
}

// ---------- split-K GEMM ----------
template<int KSLICE>
__global__ void __launch_bounds__(256)
gemm_splitk(const float* __restrict__ A, const float* __restrict__ Bw,
            float* __restrict__ Cpart, int N)
{
    constexpr int BN = 64, BK = 16;
    __shared__ float As[BK][NTOK];
    __shared__ float Bs[BK][BN];
    int tid = threadIdx.x;
    int n0 = blockIdx.x * BN;
    int kbase = blockIdx.y * KSLICE;
    int K = gridDim.y * KSLICE;
    int tx = tid & 15, ty = tid >> 4;

    u64 acc[4][4];
    #pragma unroll
    for (int i = 0; i < 4; i++)
        #pragma unroll
        for (int j = 0; j < 4; j++) acc[i][j] = 0ULL;

    for (int k0 = kbase; k0 < kbase + KSLICE; k0 += BK) {
        #pragma unroll
        for (int j = 0; j < 2; j++) {
            int lin = tid + j * 256;
            int am = lin & 127, k4 = (lin >> 7) * 4;
            float4 av = *(const float4*)&A[am * K + k0 + k4];
            As[k4+0][am] = av.x; As[k4+1][am] = av.y;
            As[k4+2][am] = av.z; As[k4+3][am] = av.w;
        }
        {
            int bk = tid >> 4, bn = (tid & 15) * 4;
            *(float4*)&Bs[bk][bn] = *(const float4*)&Bw[(k0 + bk) * N + n0 + bn];
        }
        __syncthreads();
        #pragma unroll
        for (int k = 0; k < BK; k++) {
            ulonglong2 a01 = *(const ulonglong2*)&As[k][ty*8];
            ulonglong2 a23 = *(const ulonglong2*)&As[k][ty*8 + 4];
            float4 bf = *(const float4*)&Bs[k][tx*4];
            u64 b0 = pk2(bf.x, bf.x), b1 = pk2(bf.y, bf.y);
            u64 b2 = pk2(bf.z, bf.z), b3 = pk2(bf.w, bf.w);
            acc[0][0] = ffma2(a01.x, b0, acc[0][0]);
            acc[0][1] = ffma2(a01.x, b1, acc[0][1]);
            acc[0][2] = ffma2(a01.x, b2, acc[0][2]);
            acc[0][3] = ffma2(a01.x, b3, acc[0][3]);
            acc[1][0] = ffma2(a01.y, b0, acc[1][0]);
            acc[1][1] = ffma2(a01.y, b1, acc[1][1]);
            acc[1][2] = ffma2(a01.y, b2, acc[1][2]);
            acc[1][3] = ffma2(a01.y, b3, acc[1][3]);
            acc[2][0] = ffma2(a23.x, b0, acc[2][0]);
            acc[2][1] = ffma2(a23.x, b1, acc[2][1]);
            acc[2][2] = ffma2(a23.x, b2, acc[2][2]);
            acc[2][3] = ffma2(a23.x, b3, acc[2][3]);
            acc[3][0] = ffma2(a23.y, b0, acc[3][0]);
            acc[3][1] = ffma2(a23.y, b1, acc[3][1]);
            acc[3][2] = ffma2(a23.y, b2, acc[3][2]);
            acc[3][3] = ffma2(a23.y, b3, acc[3][3]);
        }
        __syncthreads();
    }
    float* cp = Cpart + (size_t)blockIdx.y * NTOK * N;
    #pragma unroll
    for (int mp = 0; mp < 4; mp++) {
        float lo[4], hi[4];
        #pragma unroll
        for (int j = 0; j < 4; j++) upk2(acc[mp][j], lo[j], hi[j]);
        int m = ty * 8 + mp * 2;
        float4 w0 = {lo[0], lo[1], lo[2], lo[3]};
        float4 w1 = {hi[0], hi[1], hi[2], hi[3]};
        *(float4*)&cp[(m+0) * N + n0 + tx*4] = w0;
        *(float4*)&cp[(m+1) * N + n0 + tx*4] = w1;
    }
}

// ---------- split-K reduce ----------
template<int NS>
__global__ void __launch_bounds__(256)
reduce_part(const float* __restrict__ Cpart, const float* __restrict__ bias,
            float* __restrict__ C, int N)
{
    int idx = blockIdx.x * 256 + threadIdx.x;
    int n4 = N / 4;
    int m = idx / n4, n = (idx % n4) * 4;
    float4 s = *(const float4*)&bias[n];
    #pragma unroll
    for (int sp = 0; sp < NS; sp++) {
        float4 p = *(const float4*)&Cpart[(size_t)sp * NTOK * N + m * N + n];
        s.x += p.x; s.y += p.y; s.z += p.z; s.w += p.w;
    }
    *(float4*)&C[m * N + n] = s;
}

#define SCP 18

// ---------- split-KV flash attention; KV copy-out via bulk-TMA stores (R13) ----------
__global__ void __launch_bounds__(256, 3)
attn_split(const float* __restrict__ kc, const float* __restrict__ vc,
           float* __restrict__ out)
{
    extern __shared__ float sm[];
    float* Kb = sm;                       // 8192
    float* Vb = sm + 2*32*HD;             // 4096
    float* Qs = sm + 3*32*HD;             // 2048
    float* Sc = Qs + SEQ*HD;              // 32*18
    float* Ps = Sc + 32*SCP;              // 512
    float* corr_sm = Ps + SEQ*32;         // 16

    int sp = blockIdx.x, h = blockIdx.y, b = blockIdx.z;
    int tid = threadIdx.x;
    int s = tid >> 4, dg = tid & 15;      // softmax role
    int warp = tid >> 5, lane = tid & 31;
    int a_k = warp * 4 + (lane >> 3);     // stage A key
    int dc  = lane & 7;                   // stage A d-chunk
    int kh  = tid >> 7;                   // stage B key half
    int bs  = (tid >> 3) & 15;            // stage B query
    int d8  = tid & 7;                    // stage B d-chunk
    int w8 = tid >> 5;
    int c4 = (tid & 31) * 4;

    int tb = sp * 19;
    int te = min(tb + 19, 129);

    u64 bacc[8];
    #pragma unroll
    for (int j = 0; j < 8; j++) bacc[j] = 0ULL;
    float m_r = -INFINITY, l_r = 0.f;
    const float SCALE = 0.08838834764831845f;

    const float* kcb  = &kc[(size_t)(b*NH + h) * CACHE * HD];
    const float* vcb  = &vc[(size_t)(b*NH + h) * CACHE * HD];
    const float* qkvK = &g_qkv[(size_t)(b*SEQ)*DIM3 +   DIM + h*HD];
    const float* qkvV = &g_qkv[(size_t)(b*SEQ)*DIM3 + 2*DIM + h*HD];
    float* khout = &out[KH_OFF + (size_t)(b*NH + h) * TTOT * HD];
    float* vhout = &out[VH_OFF + (size_t)(b*NH + h) * TTOT * HD];

    auto issueK = [&](int tile, int bsel, bool tail) {
        float* dst = Kb + bsel * 32 * HD;
        if (!tail) {
            const float* src = kcb + (size_t)tile * 32 * HD + (size_t)w8 * HD + c4;
            #pragma unroll
            for (int i = 0; i < 4; i++)
                cpa16(dst + (w8 + 8*i)*HD + c4, src + (size_t)(8*i)*HD);
        } else {
            #pragma unroll
            for (int i = 0; i < 4; i++) {
                int rr = w8 + 8*i;
                int t = tile * 32 + rr;
                int tc = t < TTOT ? t : TTOT - 1;
                const float* src = (tc < CACHE) ? (kcb + (size_t)tc*HD + c4)
                                                : (qkvK + (size_t)(tc-CACHE)*DIM3 + c4);
                cpa16(dst + rr*HD + c4, src);
            }
        }
    };
    auto issueV = [&](int tile, bool tail) {
        if (!tail) {
            const float* src = vcb + (size_t)tile * 32 * HD + (size_t)w8 * HD + c4;
            #pragma unroll
            for (int i = 0; i < 4; i++)
                cpa16(Vb + (w8 + 8*i)*HD + c4, src + (size_t)(8*i)*HD);
        } else {
            #pragma unroll
            for (int i = 0; i < 4; i++) {
                int rr = w8 + 8*i;
                int t = tile * 32 + rr;
                int tc = t < TTOT ? t : TTOT - 1;
                const float* src = (tc < CACHE) ? (vcb + (size_t)tc*HD + c4)
                                                : (qkvV + (size_t)(tc-CACHE)*DIM3 + c4);
                cpa16(Vb + rr*HD + c4, src);
            }
        }
    };

    // stage Q tile into smem (once)
    #pragma unroll
    for (int i = 0; i < 2; i++) {
        int lin = tid + i * 256;
        int q = lin >> 5, c = (lin & 31) * 4;
        *(float4*)&Qs[q*HD + c] = *(const float4*)&g_qkv[(size_t)(b*SEQ + q)*DIM3 + h*HD + c];
    }

    // prologue
    issueK(tb, 0, false); CP_COMMIT();
    issueV(tb, false);    CP_COMMIT();
    issueK(tb + 1 < te ? tb + 1 : tb, 1, false);
    CP_COMMIT();
    CP_WAIT(2);
    __syncthreads();

    for (int tile = tb; tile < te; tile++) {
        int t0 = tile * 32;
        int buf = (tile - tb) & 1;
        const float* Kt = Kb + buf * 32 * HD;
        unsigned int tile_bytes = (tile == 128) ? 16u*HD*4u : 32u*HD*4u;

        // ---- K_i copy-out via bulk engine ----
        if (tid == 0) {
            fence_proxy_async_sh();
            bulk_store(khout + (size_t)t0 * HD, Kt, tile_bytes);
            BULK_COMMIT();
        }

        // ---- stage A ----
        {
            u64 kreg[8];
            #pragma unroll
            for (int j = 0; j < 4; j++) {
                ulonglong2 kv = *(const ulonglong2*)&Kt[a_k*HD + j*32 + dc*4];
                kreg[2*j] = kv.x; kreg[2*j+1] = kv.y;
            }
            #pragma unroll
            for (int g = 0; g < 2; g++) {
                float p[8];
                #pragma unroll
                for (int qq = 0; qq < 8; qq++) {
                    int q = g*8 + qq;
                    u64 dv = 0ULL;
                    #pragma unroll
                    for (int j = 0; j < 4; j++) {
                        ulonglong2 qv = *(const ulonglong2*)&Qs[q*HD + j*32 + dc*4];
                        dv = ffma2(kreg[2*j],   qv.x, dv);
                        dv = ffma2(kreg[2*j+1], qv.y, dv);
                    }
                    float lo, hi; upk2(dv, lo, hi);
                    p[qq] = lo + hi;
                }
                float sq = bfly8(p, dc);
                Sc[a_k*SCP + g*8 + dc] = sq;
            }
        }
        __syncthreads();

        // ---- softmax ----
        float sc0 = Sc[dg*SCP + s] * SCALE;
        float sc1 = Sc[(dg+16)*SCP + s] * SCALE;
        if (tile == 128) {
            if (t0 + dg > CACHE + s)      sc0 = -INFINITY;
            if (t0 + 16 + dg > CACHE + s) sc1 = -INFINITY;
        }
        float tmax = fmaxf(m_r, fmaxf(sc0, sc1));
        tmax = fmaxf(tmax, __shfl_xor_sync(0xffffffffu, tmax, 1));
        tmax = fmaxf(tmax, __shfl_xor_sync(0xffffffffu, tmax, 2));
        tmax = fmaxf(tmax, __shfl_xor_sync(0xffffffffu, tmax, 4));
        tmax = fmaxf(tmax, __shfl_xor_sync(0xffffffffu, tmax, 8));
        float corr = __expf(m_r - tmax);
        m_r = tmax;
        float e0 = __expf(sc0 - tmax);
        float e1 = __expf(sc1 - tmax);
        Ps[s*32 + dg]      = e0;
        Ps[s*32 + dg + 16] = e1;
        if (dg == 0) corr_sm[s] = corr;
        float lsum = e0 + e1;
        lsum += __shfl_xor_sync(0xffffffffu, lsum, 1);
        lsum += __shfl_xor_sync(0xffffffffu, lsum, 2);
        lsum += __shfl_xor_sync(0xffffffffu, lsum, 4);
        lsum += __shfl_xor_sync(0xffffffffu, lsum, 8);
        l_r = l_r * corr + lsum;

        CP_WAIT(1);
        __syncthreads();

        // ---- V_i copy-out via bulk engine ----
        if (tid == 0) {
            fence_proxy_async_sh();
            bulk_store(vhout + (size_t)t0 * HD, Vb, tile_bytes);
            BULK_COMMIT();
        }

        // ---- stage B ----
        {
            float cq = corr_sm[bs];
            u64 c2 = pk2(cq, cq);
            #pragma unroll
            for (int j = 0; j < 8; j++) bacc[j] = fmul2(bacc[j], c2);
            const float4* Pp = (const float4*)&Ps[bs*32 + kh*16];
            float4 P4[4];
            P4[0] = Pp[0]; P4[1] = Pp[1]; P4[2] = Pp[2]; P4[3] = Pp[3];
            #pragma unroll
            for (int g = 0; g < 4; g++) {
                #pragma unroll
                for (int jj = 0; jj < 4; jj++) {
                    int k = kh*16 + g*4 + jj;
                    float pj = (jj == 0) ? P4[g].x : (jj == 1) ? P4[g].y
                             : (jj == 2) ? P4[g].z : P4[g].w;
                    u64 pp = pk2(pj, pj);
                    #pragma unroll
                    for (int j = 0; j < 4; j++) {
                        ulonglong2 vv = *(const ulonglong2*)&Vb[k*HD + j*32 + d8*4];
                        bacc[2*j]   = ffma2(pp, vv.x, bacc[2*j]);
                        bacc[2*j+1] = ffma2(pp, vv.y, bacc[2*j+1]);
                    }
                }
            }
        }

        // ---- bulk engine must finish READING Kt/Vb before refill ----
        if (tid == 0) BULK_WAIT_READ0();
        __syncthreads();

        if (tile + 1 < te) issueV(tile + 1, tile + 1 == 128);
        CP_COMMIT();
        if (tile + 2 < te) issueK(tile + 2, buf, tile + 2 == 128);
        CP_COMMIT();
        CP_WAIT(2);
        __syncthreads();
    }

    if (tid == 0) BULK_WAIT_READ0();
    __syncthreads();

    int pbq = ((b*NH + h) * NSPL + sp) * SEQ;
    if (dg == 0) { g_pm[pbq + s] = m_r; g_pl[pbq + s] = l_r; }

    float* comb = Kb;
    if (kh == 1) {
        u64* dst = (u64*)&comb[(tid & 127) * 16];
        #pragma unroll
        for (int j = 0; j < 8; j++) dst[j] = bacc[j];
    }
    __syncthreads();
    if (kh == 0) {
        const u64* src = (const u64*)&comb[(tid & 127) * 16];
        #pragma unroll
        for (int j = 0; j < 8; j++) bacc[j] = fadd2(bacc[j], src[j]);
        float* orow = &g_pacc[(size_t)(pbq + bs) * HD];
        #pragma unroll
        for (int j = 0; j < 4; j++) {
            float lo0, hi0, lo1, hi1;
            upk2(bacc[2*j], lo0, hi0);
            upk2(bacc[2*j+1], lo1, hi1);
            float4 w = {lo0, hi0, lo1, hi1};
            *(float4*)&orow[j*32 + d8*4] = w;
        }
    }
    __syncthreads();
    if (tid == 0) BULK_WAIT_ALL();
}

// ---------- combine split-KV partials -> g_ctx ----------
__global__ void __launch_bounds__(256)
attn_combine()
{
    int h = blockIdx.x, b = blockIdx.y;
    int tid = threadIdx.x;
    int s = tid >> 4, dg = tid & 15;
    int base = ((b*NH + h) * NSPL) * SEQ + s;

    float m[NSPL], l[NSPL];
    #pragma unroll
    for (int sp = 0; sp < NSPL; sp++) {
        m[sp] = g_pm[base + sp*SEQ];
        l[sp] = g_pl[base + sp*SEQ];
    }
    float M = m[0];
    #pragma unroll
    for (int sp = 1; sp < NSPL; sp++) M = fmaxf(M, m[sp]);
    float L = 0.f, w[NSPL];
    #pragma unroll
    for (int sp = 0; sp < NSPL; sp++) { w[sp] = __expf(m[sp] - M); L += w[sp] * l[sp]; }

    float o[8] = {0,0,0,0,0,0,0,0};
    #pragma unroll
    for (int sp = 0; sp < NSPL; sp++) {
        size_t pb = (size_t)(base + sp*SEQ) * HD;
        float4 a0 = *(const float4*)&g_pacc[pb + 4*dg];
        float4 a1 = *(const float4*)&g_pacc[pb + 64 + 4*dg];
        o[0] += w[sp]*a0.x; o[1] += w[sp]*a0.y; o[2] += w[sp]*a0.z; o[3] += w[sp]*a0.w;
        o[4] += w[sp]*a1.x; o[5] += w[sp]*a1.y; o[6] += w[sp]*a1.z; o[7] += w[sp]*a1.w;
    }
    float inv = 1.0f / L;
    float* cb = &g_ctx[(b*SEQ + s)*DIM + h*HD];
    float4 w0 = {o[0]*inv, o[1]*inv, o[2]*inv, o[3]*inv};
    float4 w1 = {o[4]*inv, o[5]*inv, o[6]*inv, o[7]*inv};
    *(float4*)&cb[4*dg] = w0;
    *(float4*)&cb[64 + 4*dg] = w1;
}

extern "C" void kernel_launch(void* const* d_in, const int* in_sizes, int n_in,
                              void* d_out, int out_size)
{
    const float* x      = (const float*)d_in[0];
    const float* kc     = (const float*)d_in[1];
    const float* vc     = (const float*)d_in[2];
    const float* W_attn = (const float*)d_in[3];
    const float* b_attn = (const float*)d_in[4];
    const float* W_proj = (const float*)d_in[5];
    const float* b_proj = (const float*)d_in[6];
    float* out = (float*)d_out;

    float *p_qkv, *p_ctx, *p_part;
    cudaGetSymbolAddress((void**)&p_qkv,  g_qkv);
    cudaGetSymbolAddress((void**)&p_ctx,  g_ctx);
    cudaGetSymbolAddress((void**)&p_part, g_part);

    const int ATTN_SMEM = (3*32*HD + SEQ*HD + 32*SCP + SEQ*32 + 16) * 4;   // 61760 B
    cudaFuncSetAttribute(attn_split, cudaFuncAttributeMaxDynamicSharedMemorySize, ATTN_SMEM);

    // QKV: 128x2048 @ 2048x6144, split-K 8 -> 768 blocks (5.2/SM)
    gemm_splitk<256><<<dim3(DIM3/64, 8), 256>>>(x, W_attn, p_part, DIM3);
    reduce_part<8><<<(NTOK*DIM3/4)/256, 256>>>(p_part, b_attn, p_qkv, DIM3);
    attn_split<<<dim3(NSPL, NH, BATCH), 256, ATTN_SMEM>>>(kc, vc, out);
    attn_combine<<<dim3(NH, BATCH), 256>>>();
    // proj: 128x2048 @ 2048x2048, split-K 8
    gemm_splitk<256><<<dim3(DIM/64, 8), 256>>>(p_ctx, W_proj, p_part, DIM);
    reduce_part<8><<<(NTOK*DIM/4)/256, 256>>>(p_part, b_proj, out, DIM);
}

// round 17
// speedup vs baseline: 1.0780x; 1.0009x over previous
#include <cuda_runtime.h>
#include <stdint.h>
#include <math.h>

#define BATCH 8
#define SEQ   16
#define NH    16
#define HD    128
#define DIM   2048
#define DIM3  6144
#define CACHE 4096
#define TTOT  4112
#define NTOK  128
#define NSPL  7

#define KH_OFF (NTOK*DIM)
#define KH_ELEMS (BATCH*NH*TTOT*HD)
#define VH_OFF (KH_OFF + KH_ELEMS)

typedef unsigned long long u64;

__device__ float g_qkv[NTOK * DIM3];            // 3 MB
__device__ float g_ctx[NTOK * DIM];             // 1 MB
__device__ float g_part[8 * NTOK * DIM3];       // split-K partials (24 MB)
__device__ float g_pacc[BATCH*NH*NSPL*SEQ*HD];  // attn partial ctx
__device__ float g_pm[BATCH*NH*NSPL*SEQ];
__device__ float g_pl[BATCH*NH*NSPL*SEQ];

// ---------- packed f32x2 helpers (sm_103a) ----------
__device__ __forceinline__ u64 pk2(float lo, float hi) {
    u64 r; asm("mov.b64 %0, {%1, %2};" : "=l"(r) : "f"(lo), "f"(hi)); return r;
}
__device__ __forceinline__ void upk2(u64 v, float& lo, float& hi) {
    asm("mov.b64 {%0, %1}, %2;" : "=f"(lo), "=f"(hi) : "l"(v));
}
__device__ __forceinline__ u64 ffma2(u64 a, u64 b, u64 c) {
    u64 d; asm("fma.rn.f32x2 %0, %1, %2, %3;" : "=l"(d) : "l"(a), "l"(b), "l"(c)); return d;
}
__device__ __forceinline__ u64 fmul2(u64 a, u64 b) {
    u64 d; asm("mul.rn.f32x2 %0, %1, %2;" : "=l"(d) : "l"(a), "l"(b)); return d;
}
__device__ __forceinline__ u64 fadd2(u64 a, u64 b) {
    u64 d; asm("add.rn.f32x2 %0, %1, %2;" : "=l"(d) : "l"(a), "l"(b)); return d;
}

// ---------- cp.async helpers ----------
__device__ __forceinline__ void cpa16(void* smem_dst, const void* gmem_src) {
    unsigned int su = (unsigned int)__cvta_generic_to_shared(smem_dst);
    asm volatile("cp.async.cg.shared.global [%0], [%1], 16;" :: "r"(su), "l"(gmem_src));
}
#define CP_COMMIT() asm volatile("cp.async.commit_group;")
#define CP_WAIT(N)  asm volatile("cp.async.wait_group %0;" :: "n"(N))

// ---------- bulk smem->gmem copy (TMA engine) ----------
__device__ __forceinline__ void bulk_store(void* gmem_dst, const void* smem_src,
                                           unsigned int bytes) {
    unsigned int su = (unsigned int)__cvta_generic_to_shared(smem_src);
    asm volatile("cp.async.bulk.global.shared::cta.bulk_group [%0], [%1], %2;"
                 :: "l"(gmem_dst), "r"(su), "r"(bytes) : "memory");
}
#define BULK_COMMIT()     asm volatile("cp.async.bulk.commit_group;" ::: "memory")
#define BULK_WAIT_READ0() asm volatile("cp.async.bulk.wait_group.read 0;" ::: "memory")
#define BULK_WAIT_ALL()   asm volatile("cp.async.bulk.wait_group 0;" ::: "memory")
__device__ __forceinline__ void fence_proxy_async_sh() {
    asm volatile("fence.proxy.async.shared::cta;" ::: "memory");
}

// ---------- bfly8 ----------
__device__ __forceinline__ float bfly8(const float p[8], int dc) {
    const unsigned FULL = 0xffffffffu;
    bool b4 = (dc & 4) != 0;
    float r4[4];
    #pragma unroll
    for (int i = 0; i < 4; i++) {
        float send = b4 ? p[i] : p[i+4];
        float recv = __shfl_xor_sync(FULL, send, 4);
        r4[i] = (b4 ? p[i+4] : p[i]) + recv;
    }
    bool b2 = (dc & 2) != 0;
    float r2[2];
    #pragma unroll
    for (int i = 0; i < 2; i++) {
        float send = b2 ? r4[i] : r4[i+2];
        float recv = __shfl_xor_sync(FULL, send, 2);
        r2[i] = (b2 ? r4[i+2] : r4[i]) + recv;
    }
    bool b1 = (dc & 1) != 0;
    float send = b1 ? r2[0] : r2[1];
    float recv = __shfl_xor_sync(FULL, send, 1);
    return (b1 ? r2[1] : r2[0]) + recv;
}

// ---------- split-K GEMM ----------
template<int KSLICE>
__global__ void __launch_bounds__(256)
gemm_splitk(const float* __restrict__ A, const float* __restrict__ Bw,
            float* __restrict__ Cpart, int N)
{
    constexpr int BN = 64, BK = 16;
    __shared__ float As[BK][NTOK];
    __shared__ float Bs[BK][BN];
    int tid = threadIdx.x;
    int n0 = blockIdx.x * BN;
    int kbase = blockIdx.y * KSLICE;
    int K = gridDim.y * KSLICE;
    int tx = tid & 15, ty = tid >> 4;

    u64 acc[4][4];
    #pragma unroll
    for (int i = 0; i < 4; i++)
        #pragma unroll
        for (int j = 0; j < 4; j++) acc[i][j] = 0ULL;

    for (int k0 = kbase; k0 < kbase + KSLICE; k0 += BK) {
        #pragma unroll
        for (int j = 0; j < 2; j++) {
            int lin = tid + j * 256;
            int am = lin & 127, k4 = (lin >> 7) * 4;
            float4 av = *(const float4*)&A[am * K + k0 + k4];
            As[k4+0][am] = av.x; As[k4+1][am] = av.y;
            As[k4+2][am] = av.z; As[k4+3][am] = av.w;
        }
        {
            int bk = tid >> 4, bn = (tid & 15) * 4;
            *(float4*)&Bs[bk][bn] = *(const float4*)&Bw[(k0 + bk) * N + n0 + bn];
        }
        __syncthreads();
        #pragma unroll
        for (int k = 0; k < BK; k++) {
            ulonglong2 a01 = *(const ulonglong2*)&As[k][ty*8];
            ulonglong2 a23 = *(const ulonglong2*)&As[k][ty*8 + 4];
            float4 bf = *(const float4*)&Bs[k][tx*4];
            u64 b0 = pk2(bf.x, bf.x), b1 = pk2(bf.y, bf.y);
            u64 b2 = pk2(bf.z, bf.z), b3 = pk2(bf.w, bf.w);
            acc[0][0] = ffma2(a01.x, b0, acc[0][0]);
            acc[0][1] = ffma2(a01.x, b1, acc[0][1]);
            acc[0][2] = ffma2(a01.x, b2, acc[0][2]);
            acc[0][3] = ffma2(a01.x, b3, acc[0][3]);
            acc[1][0] = ffma2(a01.y, b0, acc[1][0]);
            acc[1][1] = ffma2(a01.y, b1, acc[1][1]);
            acc[1][2] = ffma2(a01.y, b2, acc[1][2]);
            acc[1][3] = ffma2(a01.y, b3, acc[1][3]);
            acc[2][0] = ffma2(a23.x, b0, acc[2][0]);
            acc[2][1] = ffma2(a23.x, b1, acc[2][1]);
            acc[2][2] = ffma2(a23.x, b2, acc[2][2]);
            acc[2][3] = ffma2(a23.x, b3, acc[2][3]);
            acc[3][0] = ffma2(a23.y, b0, acc[3][0]);
            acc[3][1] = ffma2(a23.y, b1, acc[3][1]);
            acc[3][2] = ffma2(a23.y, b2, acc[3][2]);
            acc[3][3] = ffma2(a23.y, b3, acc[3][3]);
        }
        __syncthreads();
    }
    float* cp = Cpart + (size_t)blockIdx.y * NTOK * N;
    #pragma unroll
    for (int mp = 0; mp < 4; mp++) {
        float lo[4], hi[4];
        #pragma unroll
        for (int j = 0; j < 4; j++) upk2(acc[mp][j], lo[j], hi[j]);
        int m = ty * 8 + mp * 2;
        float4 w0 = {lo[0], lo[1], lo[2], lo[3]};
        float4 w1 = {hi[0], hi[1], hi[2], hi[3]};
        *(float4*)&cp[(m+0) * N + n0 + tx*4] = w0;
        *(float4*)&cp[(m+1) * N + n0 + tx*4] = w1;
    }
}

// ---------- split-K reduce ----------
template<int NS>
__global__ void __launch_bounds__(256)
reduce_part(const float* __restrict__ Cpart, const float* __restrict__ bias,
            float* __restrict__ C, int N)
{
    int idx = blockIdx.x * 256 + threadIdx.x;
    int n4 = N / 4;
    int m = idx / n4, n = (idx % n4) * 4;
    float4 s = *(const float4*)&bias[n];
    #pragma unroll
    for (int sp = 0; sp < NS; sp++) {
        float4 p = *(const float4*)&Cpart[(size_t)sp * NTOK * N + m * N + n];
        s.x += p.x; s.y += p.y; s.z += p.z; s.w += p.w;
    }
    *(float4*)&C[m * N + n] = s;
}

#define SCP 18

// ---------- split-KV flash attention; KV copy-out via bulk-TMA stores (R13) ----------
__global__ void __launch_bounds__(256, 3)
attn_split(const float* __restrict__ kc, const float* __restrict__ vc,
           float* __restrict__ out)
{
    extern __shared__ float sm[];
    float* Kb = sm;                       // 8192
    float* Vb = sm + 2*32*HD;             // 4096
    float* Qs = sm + 3*32*HD;             // 2048
    float* Sc = Qs + SEQ*HD;              // 32*18
    float* Ps = Sc + 32*SCP;              // 512
    float* corr_sm = Ps + SEQ*32;         // 16

    int sp = blockIdx.x, h = blockIdx.y, b = blockIdx.z;
    int tid = threadIdx.x;
    int s = tid >> 4, dg = tid & 15;      // softmax role
    int warp = tid >> 5, lane = tid & 31;
    int a_k = warp * 4 + (lane >> 3);     // stage A key
    int dc  = lane & 7;                   // stage A d-chunk
    int kh  = tid >> 7;                   // stage B key half
    int bs  = (tid >> 3) & 15;            // stage B query
    int d8  = tid & 7;                    // stage B d-chunk
    int w8 = tid >> 5;
    int c4 = (tid & 31) * 4;

    int tb = sp * 19;
    int te = min(tb + 19, 129);

    u64 bacc[8];
    #pragma unroll
    for (int j = 0; j < 8; j++) bacc[j] = 0ULL;
    float m_r = -INFINITY, l_r = 0.f;
    const float SCALE = 0.08838834764831845f;

    const float* kcb  = &kc[(size_t)(b*NH + h) * CACHE * HD];
    const float* vcb  = &vc[(size_t)(b*NH + h) * CACHE * HD];
    const float* qkvK = &g_qkv[(size_t)(b*SEQ)*DIM3 +   DIM + h*HD];
    const float* qkvV = &g_qkv[(size_t)(b*SEQ)*DIM3 + 2*DIM + h*HD];
    float* khout = &out[KH_OFF + (size_t)(b*NH + h) * TTOT * HD];
    float* vhout = &out[VH_OFF + (size_t)(b*NH + h) * TTOT * HD];

    auto issueK = [&](int tile, int bsel, bool tail) {
        float* dst = Kb + bsel * 32 * HD;
        if (!tail) {
            const float* src = kcb + (size_t)tile * 32 * HD + (size_t)w8 * HD + c4;
            #pragma unroll
            for (int i = 0; i < 4; i++)
                cpa16(dst + (w8 + 8*i)*HD + c4, src + (size_t)(8*i)*HD);
        } else {
            #pragma unroll
            for (int i = 0; i < 4; i++) {
                int rr = w8 + 8*i;
                int t = tile * 32 + rr;
                int tc = t < TTOT ? t : TTOT - 1;
                const float* src = (tc < CACHE) ? (kcb + (size_t)tc*HD + c4)
                                                : (qkvK + (size_t)(tc-CACHE)*DIM3 + c4);
                cpa16(dst + rr*HD + c4, src);
            }
        }
    };
    auto issueV = [&](int tile, bool tail) {
        if (!tail) {
            const float* src = vcb + (size_t)tile * 32 * HD + (size_t)w8 * HD + c4;
            #pragma unroll
            for (int i = 0; i < 4; i++)
                cpa16(Vb + (w8 + 8*i)*HD + c4, src + (size_t)(8*i)*HD);
        } else {
            #pragma unroll
            for (int i = 0; i < 4; i++) {
                int rr = w8 + 8*i;
                int t = tile * 32 + rr;
                int tc = t < TTOT ? t : TTOT - 1;
                const float* src = (tc < CACHE) ? (vcb + (size_t)tc*HD + c4)
                                                : (qkvV + (size_t)(tc-CACHE)*DIM3 + c4);
                cpa16(Vb + rr*HD + c4, src);
            }
        }
    };

    // stage Q tile into smem (once)
    #pragma unroll
    for (int i = 0; i < 2; i++) {
        int lin = tid + i * 256;
        int q = lin >> 5, c = (lin & 31) * 4;
        *(float4*)&Qs[q*HD + c] = *(const float4*)&g_qkv[(size_t)(b*SEQ + q)*DIM3 + h*HD + c];
    }

    // prologue
    issueK(tb, 0, false); CP_COMMIT();
    issueV(tb, false);    CP_COMMIT();
    issueK(tb + 1 < te ? tb + 1 : tb, 1, false);
    CP_COMMIT();
    CP_WAIT(2);
    __syncthreads();

    for (int tile = tb; tile < te; tile++) {
        int t0 = tile * 32;
        int buf = (tile - tb) & 1;
        const float* Kt = Kb + buf * 32 * HD;
        unsigned int tile_bytes = (tile == 128) ? 16u*HD*4u : 32u*HD*4u;

        // ---- K_i copy-out via bulk engine ----
        if (tid == 0) {
            fence_proxy_async_sh();
            bulk_store(khout + (size_t)t0 * HD, Kt, tile_bytes);
            BULK_COMMIT();
        }

        // ---- stage A ----
        {
            u64 kreg[8];
            #pragma unroll
            for (int j = 0; j < 4; j++) {
                ulonglong2 kv = *(const ulonglong2*)&Kt[a_k*HD + j*32 + dc*4];
                kreg[2*j] = kv.x; kreg[2*j+1] = kv.y;
            }
            #pragma unroll
            for (int g = 0; g < 2; g++) {
                float p[8];
                #pragma unroll
                for (int qq = 0; qq < 8; qq++) {
                    int q = g*8 + qq;
                    u64 dv = 0ULL;
                    #pragma unroll
                    for (int j = 0; j < 4; j++) {
                        ulonglong2 qv = *(const ulonglong2*)&Qs[q*HD + j*32 + dc*4];
                        dv = ffma2(kreg[2*j],   qv.x, dv);
                        dv = ffma2(kreg[2*j+1], qv.y, dv);
                    }
                    float lo, hi; upk2(dv, lo, hi);
                    p[qq] = lo + hi;
                }
                float sq = bfly8(p, dc);
                Sc[a_k*SCP + g*8 + dc] = sq;
            }
        }
        __syncthreads();

        // ---- softmax ----
        float sc0 = Sc[dg*SCP + s] * SCALE;
        float sc1 = Sc[(dg+16)*SCP + s] * SCALE;
        if (tile == 128) {
            if (t0 + dg > CACHE + s)      sc0 = -INFINITY;
            if (t0 + 16 + dg > CACHE + s) sc1 = -INFINITY;
        }
        float tmax = fmaxf(m_r, fmaxf(sc0, sc1));
        tmax = fmaxf(tmax, __shfl_xor_sync(0xffffffffu, tmax, 1));
        tmax = fmaxf(tmax, __shfl_xor_sync(0xffffffffu, tmax, 2));
        tmax = fmaxf(tmax, __shfl_xor_sync(0xffffffffu, tmax, 4));
        tmax = fmaxf(tmax, __shfl_xor_sync(0xffffffffu, tmax, 8));
        float corr = __expf(m_r - tmax);
        m_r = tmax;
        float e0 = __expf(sc0 - tmax);
        float e1 = __expf(sc1 - tmax);
        Ps[s*32 + dg]      = e0;
        Ps[s*32 + dg + 16] = e1;
        if (dg == 0) corr_sm[s] = corr;
        float lsum = e0 + e1;
        lsum += __shfl_xor_sync(0xffffffffu, lsum, 1);
        lsum += __shfl_xor_sync(0xffffffffu, lsum, 2);
        lsum += __shfl_xor_sync(0xffffffffu, lsum, 4);
        lsum += __shfl_xor_sync(0xffffffffu, lsum, 8);
        l_r = l_r * corr + lsum;

        CP_WAIT(1);
        __syncthreads();

        // ---- V_i copy-out via bulk engine ----
        if (tid == 0) {
            fence_proxy_async_sh();
            bulk_store(vhout + (size_t)t0 * HD, Vb, tile_bytes);
            BULK_COMMIT();
        }

        // ---- stage B ----
        {
            float cq = corr_sm[bs];
            u64 c2 = pk2(cq, cq);
            #pragma unroll
            for (int j = 0; j < 8; j++) bacc[j] = fmul2(bacc[j], c2);
            const float4* Pp = (const float4*)&Ps[bs*32 + kh*16];
            float4 P4[4];
            P4[0] = Pp[0]; P4[1] = Pp[1]; P4[2] = Pp[2]; P4[3] = Pp[3];
            #pragma unroll
            for (int g = 0; g < 4; g++) {
                #pragma unroll
                for (int jj = 0; jj < 4; jj++) {
                    int k = kh*16 + g*4 + jj;
                    float pj = (jj == 0) ? P4[g].x : (jj == 1) ? P4[g].y
                             : (jj == 2) ? P4[g].z : P4[g].w;
                    u64 pp = pk2(pj, pj);
                    #pragma unroll
                    for (int j = 0; j < 4; j++) {
                        ulonglong2 vv = *(const ulonglong2*)&Vb[k*HD + j*32 + d8*4];
                        bacc[2*j]   = ffma2(pp, vv.x, bacc[2*j]);
                        bacc[2*j+1] = ffma2(pp, vv.y, bacc[2*j+1]);
                    }
                }
            }
        }

        // ---- bulk engine must finish READING Kt/Vb before refill ----
        if (tid == 0) BULK_WAIT_READ0();
        __syncthreads();

        if (tile + 1 < te) issueV(tile + 1, tile + 1 == 128);
        CP_COMMIT();
        if (tile + 2 < te) issueK(tile + 2, buf, tile + 2 == 128);
        CP_COMMIT();
        CP_WAIT(2);
        __syncthreads();
    }

    if (tid == 0) BULK_WAIT_READ0();
    __syncthreads();

    int pbq = ((b*NH + h) * NSPL + sp) * SEQ;
    if (dg == 0) { g_pm[pbq + s] = m_r; g_pl[pbq + s] = l_r; }

    float* comb = Kb;
    if (kh == 1) {
        u64* dst = (u64*)&comb[(tid & 127) * 16];
        #pragma unroll
        for (int j = 0; j < 8; j++) dst[j] = bacc[j];
    }
    __syncthreads();
    if (kh == 0) {
        const u64* src = (const u64*)&comb[(tid & 127) * 16];
        #pragma unroll
        for (int j = 0; j < 8; j++) bacc[j] = fadd2(bacc[j], src[j]);
        float* orow = &g_pacc[(size_t)(pbq + bs) * HD];
        #pragma unroll
        for (int j = 0; j < 4; j++) {
            float lo0, hi0, lo1, hi1;
            upk2(bacc[2*j], lo0, hi0);
            upk2(bacc[2*j+1], lo1, hi1);
            float4 w = {lo0, hi0, lo1, hi1};
            *(float4*)&orow[j*32 + d8*4] = w;
        }
    }
    __syncthreads();
    if (tid == 0) BULK_WAIT_ALL();
}

// ---------- combine split-KV partials -> g_ctx ----------
__global__ void __launch_bounds__(256)
attn_combine()
{
    int h = blockIdx.x, b = blockIdx.y;
    int tid = threadIdx.x;
    int s = tid >> 4, dg = tid & 15;
    int base = ((b*NH + h) * NSPL) * SEQ + s;

    float m[NSPL], l[NSPL];
    #pragma unroll
    for (int sp = 0; sp < NSPL; sp++) {
        m[sp] = g_pm[base + sp*SEQ];
        l[sp] = g_pl[base + sp*SEQ];
    }
    float M = m[0];
    #pragma unroll
    for (int sp = 1; sp < NSPL; sp++) M = fmaxf(M, m[sp]);
    float L = 0.f, w[NSPL];
    #pragma unroll
    for (int sp = 0; sp < NSPL; sp++) { w[sp] = __expf(m[sp] - M); L += w[sp] * l[sp]; }

    float o[8] = {0,0,0,0,0,0,0,0};
    #pragma unroll
    for (int sp = 0; sp < NSPL; sp++) {
        size_t pb = (size_t)(base + sp*SEQ) * HD;
        float4 a0 = *(const float4*)&g_pacc[pb + 4*dg];
        float4 a1 = *(const float4*)&g_pacc[pb + 64 + 4*dg];
        o[0] += w[sp]*a0.x; o[1] += w[sp]*a0.y; o[2] += w[sp]*a0.z; o[3] += w[sp]*a0.w;
        o[4] += w[sp]*a1.x; o[5] += w[sp]*a1.y; o[6] += w[sp]*a1.z; o[7] += w[sp]*a1.w;
    }
    float inv = 1.0f / L;
    float* cb = &g_ctx[(b*SEQ + s)*DIM + h*HD];
    float4 w0 = {o[0]*inv, o[1]*inv, o[2]*inv, o[3]*inv};
    float4 w1 = {o[4]*inv, o[5]*inv, o[6]*inv, o[7]*inv};
    *(float4*)&cb[4*dg] = w0;
    *(float4*)&cb[64 + 4*dg] = w1;
}

extern "C" void kernel_launch(void* const* d_in, const int* in_sizes, int n_in,
                              void* d_out, int out_size)
{
    const float* x      = (const float*)d_in[0];
    const float* kc     = (const float*)d_in[1];
    const float* vc     = (const float*)d_in[2];
    const float* W_attn = (const float*)d_in[3];
    const float* b_attn = (const float*)d_in[4];
    const float* W_proj = (const float*)d_in[5];
    const float* b_proj = (const float*)d_in[6];
    float* out = (float*)d_out;

    float *p_qkv, *p_ctx, *p_part;
    cudaGetSymbolAddress((void**)&p_qkv,  g_qkv);
    cudaGetSymbolAddress((void**)&p_ctx,  g_ctx);
    cudaGetSymbolAddress((void**)&p_part, g_part);

    const int ATTN_SMEM = (3*32*HD + SEQ*HD + 32*SCP + SEQ*32 + 16) * 4;   // 61760 B
    cudaFuncSetAttribute(attn_split, cudaFuncAttributeMaxDynamicSharedMemorySize, ATTN_SMEM);

    // QKV: 128x2048 @ 2048x6144, split-K 8 -> 768 blocks
    gemm_splitk<256><<<dim3(DIM3/64, 8), 256>>>(x, W_attn, p_part, DIM3);
    reduce_part<8><<<(NTOK*DIM3/4)/256, 256>>>(p_part, b_attn, p_qkv, DIM3);
    attn_split<<<dim3(NSPL, NH, BATCH), 256, ATTN_SMEM>>>(kc, vc, out);
    attn_combine<<<dim3(NH, BATCH), 256>>>();
    // proj: 128x2048 @ 2048x2048, split-K 16 -> 512 blocks (1.15 waves)
    gemm_splitk<128><<<dim3(DIM/64, 16), 256>>>(p_ctx, W_proj, p_part, DIM);
    reduce_part<16><<<(NTOK*DIM/4)/256, 256>>>(p_part, b_proj, out, DIM);
}